// round 1
// baseline (speedup 1.0000x reference)
#include <cuda_runtime.h>

#define KK    5
#define B     4
#define H     352
#define W     1216
#define HP    (H + 4)   // 356
#define WP    (W + 4)   // 1220
#define TX    32
#define TY    4
#define TCOLS (TX * 4)      // 128 weight columns per block
#define SM_W  (TCOLS + 4)   // 132
#define SM_H  (TY + 4)      // 8
#define NJ    305           // number of 4-wide column groups (c0 = 0..1216 step 4)

__global__ __launch_bounds__(TX * TY)
void cspn_kernel(const float* __restrict__ gw,
                 const float* __restrict__ hn,
                 const float* __restrict__ h0,
                 float* __restrict__ out)
{
    __shared__ float sh[SM_H][SM_W];

    const int tx = threadIdx.x;
    const int ty = threadIdx.y;
    const int tid = ty * TX + tx;
    const int bx = blockIdx.x;
    const int by = blockIdx.y;
    const int b  = blockIdx.z;

    const int Y0 = by * TY;
    const int colbase = TCOLS * bx - 4;   // first hn column cached in smem

    // ---- cooperative hn tile load: rows [Y0-2, Y0+TY+1], cols [colbase, colbase+131]
    const float* __restrict__ hnb = hn + b * (H * W);
    #pragma unroll
    for (int i = tid; i < SM_H * SM_W; i += TX * TY) {
        const int r = i / SM_W;
        const int c = i - r * SM_W;
        const int gy = Y0 - 2 + r;
        const int gx = colbase + c;
        float v = 0.0f;
        if (gy >= 0 && gy < H && gx >= 0 && gx < W) v = hnb[gy * W + gx];
        sh[r][c] = v;
    }
    __syncthreads();

    const int j = bx * TX + tx;          // global 4-wide column group
    if (j >= NJ) return;                 // no further barriers below — safe

    const int c0 = 4 * j;                // weight column base; outputs x = c0-2+i
    const int y  = Y0 + ty;              // H = 352 divisible by TY -> no guard

    // ---- center-tap source (h0), per-output
    const float* __restrict__ h0b = h0 + b * (H * W) + y * W;
    float hv0 = 0.f, hv1 = 0.f, hv2 = 0.f, hv3 = 0.f;
    {
        const int x0 = c0 - 2;
        if (x0     >= 0 && x0     < W) hv0 = h0b[x0];
        if (x0 + 1 >= 0 && x0 + 1 < W) hv1 = h0b[x0 + 1];
        if (x0 + 2 < W)                hv2 = h0b[x0 + 2];
        if (x0 + 3 < W)                hv3 = h0b[x0 + 3];
    }

    float acc0 = 0.f, acc1 = 0.f, acc2 = 0.f, acc3 = 0.f;

    // weight base for this thread: gw[b, t=0, y+2, c0]; tap t adds t*HP*WP
    const float* __restrict__ gwb = gw + (b * 25) * (HP * WP) + (y + 2) * WP + c0;

    #pragma unroll
    for (int dy = 0; dy < KK; dy++) {
        const int srow = ty + 4 - dy;    // smem row for hn row (y+2-dy)
        // 9-wide slice covering all dx taps for the 4 outputs:
        // s[k] = sh[srow][4*tx + k]  (16B-aligned -> two LDS.128 + one LDS.32)
        const float* srp = &sh[srow][4 * tx];
        const float4 v0 = *reinterpret_cast<const float4*>(srp);
        const float4 v1 = *reinterpret_cast<const float4*>(srp + 4);
        const float s8 = srp[8];
        float s[9] = { v0.x, v0.y, v0.z, v0.w, v1.x, v1.y, v1.z, v1.w, s8 };

        #pragma unroll
        for (int dx = 0; dx < KK; dx++) {
            const int t = dy * KK + dx;
            const float4 w4 = *reinterpret_cast<const float4*>(gwb + t * (HP * WP));
            if (t == 12) {               // center tap uses h0
                acc0 = fmaf(w4.x, hv0, acc0);
                acc1 = fmaf(w4.y, hv1, acc1);
                acc2 = fmaf(w4.z, hv2, acc2);
                acc3 = fmaf(w4.w, hv3, acc3);
            } else {
                const int o = 4 - dx;    // s[o+i] = hn[y+2-dy][x+2-dx] for output i
                acc0 = fmaf(w4.x, s[o],     acc0);
                acc1 = fmaf(w4.y, s[o + 1], acc1);
                acc2 = fmaf(w4.z, s[o + 2], acc2);
                acc3 = fmaf(w4.w, s[o + 3], acc3);
            }
        }
    }

    // ---- guarded stores (edges of the shifted-by-2 window)
    float* __restrict__ ob = out + b * (H * W) + y * W;
    const int x0 = c0 - 2;
    if (x0     >= 0 && x0     < W) ob[x0]     = acc0;
    if (x0 + 1 >= 0 && x0 + 1 < W) ob[x0 + 1] = acc1;
    if (x0 + 2 < W)                ob[x0 + 2] = acc2;
    if (x0 + 3 < W)                ob[x0 + 3] = acc3;
}

extern "C" void kernel_launch(void* const* d_in, const int* in_sizes, int n_in,
                              void* d_out, int out_size)
{
    const float* gw = (const float*)d_in[0];  // guide_weight (4,25,356,1220)
    const float* hn = (const float*)d_in[1];  // (4,1,352,1216)
    const float* h0 = (const float*)d_in[2];  // (4,1,352,1216)
    float* out = (float*)d_out;               // (4,1,352,1216)

    dim3 block(TX, TY);
    dim3 grid((NJ + TX - 1) / TX, H / TY, B); // (10, 88, 4)
    cspn_kernel<<<grid, block>>>(gw, hn, h0, out);
}

// round 3
// speedup vs baseline: 1.1718x; 1.1718x over previous
#include <cuda_runtime.h>

#define KK    5
#define B     4
#define H     352
#define W     1216
#define HP    (H + 4)   // 356
#define WP    (W + 4)   // 1220
#define TX    32
#define TY    4
#define TCOLS (TX * 2)      // 64 weight columns per block
#define SM_W  (TCOLS + 4)   // 68
#define SM_H  (TY + 4)      // 8
#define NJ    609           // 2-wide column groups: c0 = 0,2,...,1216
#define NBX   20            // ceil(NJ/TX)

__global__ __launch_bounds__(TX * TY, 12)
void cspn_kernel(const float* __restrict__ gw,
                 const float* __restrict__ hn,
                 const float* __restrict__ h0,
                 float* __restrict__ out)
{
    __shared__ float sh[SM_H][SM_W];

    const int tx = threadIdx.x;
    const int ty = threadIdx.y;
    const int tid = ty * TX + tx;
    const int bx = blockIdx.x;
    const int by = blockIdx.y;
    const int b  = blockIdx.z;

    const int Y0 = by * TY;
    const int colbase = TCOLS * bx - 4;   // first hn column cached in smem

    // ---- cooperative hn tile: rows [Y0-2, Y0+TY+1], cols [colbase, colbase+67]
    const float* __restrict__ hnb = hn + b * (H * W);
    #pragma unroll
    for (int i = tid; i < SM_H * SM_W; i += TX * TY) {
        const int r = i / SM_W;
        const int c = i - r * SM_W;
        const int gy = Y0 - 2 + r;
        const int gx = colbase + c;
        float v = 0.0f;
        if (gy >= 0 && gy < H && gx >= 0 && gx < W) v = hnb[gy * W + gx];
        sh[r][c] = v;
    }
    __syncthreads();

    const int j = bx * TX + tx;          // global 2-wide column group
    if (j >= NJ) return;                 // no barriers below — safe

    const int c0 = 2 * j;                // weight column base; outputs x = c0-2, c0-1
    const int y  = Y0 + ty;              // H divisible by TY -> no guard

    // ---- center-tap source (h0)
    const float* __restrict__ h0b = h0 + b * (H * W) + y * W;
    const int x0 = c0 - 2;
    float hv0 = 0.f, hv1 = 0.f;
    if (x0     >= 0 && x0     < W) hv0 = h0b[x0];
    if (x0 + 1 >= 0 && x0 + 1 < W) hv1 = h0b[x0 + 1];

    float acc0 = 0.f, acc1 = 0.f;

    // weight base: gw[b, t=0, y+2, c0]; tap t adds t*HP*WP
    const float* __restrict__ gwb = gw + (b * 25) * (HP * WP) + (y + 2) * WP + c0;

    #pragma unroll
    for (int dy = 0; dy < KK; dy++) {
        const int srow = ty + 4 - dy;    // smem row for hn row (y+2-dy)
        // 6-wide slice: s[k] = hn col (c0-4+k); 8B-aligned base (2*tx even)
        const float* srp = &sh[srow][2 * tx];
        const float2 p0 = *reinterpret_cast<const float2*>(srp);
        const float2 p1 = *reinterpret_cast<const float2*>(srp + 2);
        const float2 p2 = *reinterpret_cast<const float2*>(srp + 4);
        const float s[6] = { p0.x, p0.y, p1.x, p1.y, p2.x, p2.y };

        #pragma unroll
        for (int dx = 0; dx < KK; dx++) {
            const int t = dy * KK + dx;
            const float2 w2 = *reinterpret_cast<const float2*>(gwb + t * (HP * WP));
            if (t == 12) {               // center tap uses h0
                acc0 = fmaf(w2.x, hv0, acc0);
                acc1 = fmaf(w2.y, hv1, acc1);
            } else {
                const int o = 4 - dx;    // s[o+i] = hn[y+2-dy][x+2-dx] for output i
                acc0 = fmaf(w2.x, s[o],     acc0);
                acc1 = fmaf(w2.y, s[o + 1], acc1);
            }
        }
    }

    // ---- stores (x0 even -> 8B-aligned float2 in the interior)
    float* __restrict__ ob = out + b * (H * W) + y * W;
    if (x0 >= 0) {
        // x0+1 <= 1215 < W always holds when x0 >= 0
        *reinterpret_cast<float2*>(ob + x0) = make_float2(acc0, acc1);
    }
    // j == 0 produces x = -2,-1: nothing to store
}

extern "C" void kernel_launch(void* const* d_in, const int* in_sizes, int n_in,
                              void* d_out, int out_size)
{
    const float* gw = (const float*)d_in[0];  // guide_weight (4,25,356,1220)
    const float* hn = (const float*)d_in[1];  // (4,1,352,1216)
    const float* h0 = (const float*)d_in[2];  // (4,1,352,1216)
    float* out = (float*)d_out;               // (4,1,352,1216)

    dim3 block(TX, TY);
    dim3 grid(NBX, H / TY, B);                // (20, 88, 4) = 7040 CTAs
    cspn_kernel<<<grid, block>>>(gw, hn, h0, out);
}